// round 7
// baseline (speedup 1.0000x reference)
#include <cuda_runtime.h>
#include <cuda_bf16.h>
#include <cstdint>
#include <cstddef>

#define NN 100000
#define NE 600000
#define NF 64
#define EF 16
#define EH 128
#define NSTEPS 6

// ---- scratch (device globals; no allocation allowed) ----
__device__ float    g_P  [(size_t)NN * EH];   // nf@W1 + b1
__device__ float    g_U1 [(size_t)NN * EH];   // nf@U1 + b1
__device__ uint32_t g_Bh [(size_t)NE * 64];   // B' hi (bf16x2 per 2 cols)
__device__ uint32_t g_Bl [(size_t)NE * 64];   // B' lo
__device__ uint32_t g_Gh0[(size_t)NE * 64];   // G ping hi
__device__ uint32_t g_Gl0[(size_t)NE * 64];   // G ping lo
__device__ uint32_t g_Gh1[(size_t)NE * 64];   // G pong hi
__device__ uint32_t g_Gl1[(size_t)NE * 64];   // G pong lo
__device__ float    g_T0 [(size_t)NN * EH];   // T ping
__device__ float    g_T1 [(size_t)NN * EH];   // T pong
__device__ uint32_t g_W3h[128 * 64];          // W3^T hi, bf16x2 packed along k
__device__ uint32_t g_W3l[128 * 64];          // W3^T lo
__device__ uint32_t g_U2h[128 * 64];          // U2^T hi
__device__ uint32_t g_U2l[128 * 64];          // U2^T lo
__device__ float    g_cb [EH];                // W2_b + W3_b

// ================= helpers =================
__device__ __forceinline__ void mma16(float* c, const uint32_t* a,
                                      uint32_t b0, uint32_t b1) {
    asm volatile(
        "mma.sync.aligned.m16n8k16.row.col.f32.bf16.bf16.f32 "
        "{%0,%1,%2,%3}, {%4,%5,%6,%7}, {%8,%9}, {%0,%1,%2,%3};"
        : "+f"(c[0]), "+f"(c[1]), "+f"(c[2]), "+f"(c[3])
        : "r"(a[0]), "r"(a[1]), "r"(a[2]), "r"(a[3]), "r"(b0), "r"(b1));
}

__device__ __forceinline__ void red2(float* p, float x, float y) {
    asm volatile("red.global.add.v2.f32 [%0], {%1, %2};"
                 :: "l"(p), "f"(x), "f"(y) : "memory");
}

// split fp32 pair into bf16x2 hi + bf16x2 lo (packed 32-bit words)
__device__ __forceinline__ void split2(float x, float y, uint32_t& hi, uint32_t& lo) {
    __nv_bfloat162 h = __floats2bfloat162_rn(x, y);
    float2 hf = __bfloat1622float2(h);
    __nv_bfloat162 l = __floats2bfloat162_rn(x - hf.x, y - hf.y);
    hi = *(uint32_t*)&h;
    lo = *(uint32_t*)&l;
}

// unpack hi/lo bf16x2 words into compensated fp32 pair
__device__ __forceinline__ float2 up2(uint32_t h, uint32_t l) {
    float2 a = __bfloat1622float2(*(__nv_bfloat162*)&h);
    float2 b = __bfloat1622float2(*(__nv_bfloat162*)&l);
    return make_float2(a.x + b.x, a.y + b.y);
}

// one launch: pack W3^T, U2^T (hi/lo), and combined bias
__global__ void prep_all(const float* __restrict__ W3, const float* __restrict__ U2,
                         const float* __restrict__ W2b, const float* __restrict__ W3b,
                         uint32_t* __restrict__ W3h, uint32_t* __restrict__ W3l,
                         uint32_t* __restrict__ U2h, uint32_t* __restrict__ U2l,
                         float* __restrict__ cb) {
    int b = blockIdx.x, tid = threadIdx.x;
    if (b < 64) {
        const float* W = (b < 32) ? W3 : U2;
        uint32_t* oh = (b < 32) ? W3h : U2h;
        uint32_t* ol = (b < 32) ? W3l : U2l;
        int idx = (b & 31) * 256 + tid;          // 0..8191
        int n = idx >> 6, kp = idx & 63;
        float v0 = W[(kp * 2 + 0) * 128 + n];
        float v1 = W[(kp * 2 + 1) * 128 + n];
        uint32_t hi, lo;
        split2(v0, v1, hi, lo);
        oh[idx] = hi; ol[idx] = lo;
    } else {
        if (tid < EH) cb[tid] = W2b[tid] + W3b[tid];
    }
}

// ============================================================
// Fused 3xBF16 MMA GEMM over edges. Tile: 64 rows x 128 cols, K=128.
// A row e built on the fly (B', G stored as compensated bf16 hi/lo):
//   FIRST:  a = relu(B'[e])
//   else :  a = relu(B'[e] + Tprev[from[e]] - Gprev[e^1])
// Epilogue:
//   STEP (!OUT): Gout[e] = split(acc) ; red.v2 Acc[from[e]] += acc
//   OUT        : red.v2 Acc[to[e]] += acc + obias
// ============================================================
static constexpr int STR = 68;                        // words (bf16x2) per row, padded
static constexpr int OFF_AH = 0;                      // [64][68]
static constexpr int OFF_AL = 64 * STR;
static constexpr int OFF_WH = 2 * 64 * STR;           // [128][68]
static constexpr int OFF_WL = 2 * 64 * STR + 128 * STR;
static constexpr int SM_WORDS = OFF_WL + 128 * STR;
static constexpr size_t SM_TOT = (size_t)SM_WORDS * 4;  // 104448 B

template <bool FIRST, bool OUT>
__global__ void __launch_bounds__(256, 2)
gemm_fused(const uint32_t* __restrict__ Bh, const uint32_t* __restrict__ Bl,
           const float* __restrict__ Tprev,
           const uint32_t* __restrict__ Gph, const uint32_t* __restrict__ Gpl,
           const uint32_t* __restrict__ Wh, const uint32_t* __restrict__ Wl,
           const int* __restrict__ from, const int* __restrict__ scat,
           const float* __restrict__ obias,
           uint32_t* __restrict__ Goh, uint32_t* __restrict__ Gol,
           float* __restrict__ Acc)
{
    extern __shared__ uint32_t smem[];
    uint32_t* Ah  = smem + OFF_AH;
    uint32_t* Al  = smem + OFF_AL;
    uint32_t* Wsh = smem + OFF_WH;
    uint32_t* Wsl = smem + OFF_WL;

    const int tid = threadIdx.x;
    const int r0  = blockIdx.x * 64;

    // ---- stage W hi/lo ----
#pragma unroll
    for (int i = 0; i < 8; ++i) {
        int f = tid + i * 256;               // 0..2047 uint4s over 8192 words
        int n = f >> 4, c = (f & 15) * 4;
        uint4 vh = *(const uint4*)(Wh + n * 64 + c);
        uint4 vl = *(const uint4*)(Wl + n * 64 + c);
        *(uint4*)(Wsh + n * STR + c) = vh;
        *(uint4*)(Wsl + n * STR + c) = vl;
    }
    // ---- stage A with fused combine + bf16 split ----
#pragma unroll
    for (int i = 0; i < 8; ++i) {
        int f   = tid + i * 256;             // 0..2047 quads of floats
        int row = f >> 5, c4 = (f & 31) * 4; // float col (mult of 4)
        int e   = r0 + row;
        size_t wb = (size_t)e * 64 + (c4 >> 1);
        uint2 bh = *(const uint2*)(Bh + wb);
        uint2 bl = *(const uint2*)(Bl + wb);
        float2 b0 = up2(bh.x, bl.x);
        float2 b1 = up2(bh.y, bl.y);
        float4 v;
        if constexpr (FIRST) {
            v.x = fmaxf(b0.x, 0.f); v.y = fmaxf(b0.y, 0.f);
            v.z = fmaxf(b1.x, 0.f); v.w = fmaxf(b1.y, 0.f);
        } else {
            int u = __ldg(&from[e]);
            float4 t = *(const float4*)(Tprev + (size_t)u * EH + c4);
            size_t gb = (size_t)(e ^ 1) * 64 + (c4 >> 1);
            uint2 gh = *(const uint2*)(Gph + gb);
            uint2 gl = *(const uint2*)(Gpl + gb);
            float2 g0 = up2(gh.x, gl.x);
            float2 g1 = up2(gh.y, gl.y);
            v.x = fmaxf(b0.x + t.x - g0.x, 0.f);
            v.y = fmaxf(b0.y + t.y - g0.y, 0.f);
            v.z = fmaxf(b1.x + t.z - g1.x, 0.f);
            v.w = fmaxf(b1.y + t.w - g1.y, 0.f);
        }
        uint32_t h0, l0, h1, l1;
        split2(v.x, v.y, h0, l0);
        split2(v.z, v.w, h1, l1);
        int sb = row * STR + (c4 >> 1);
        Ah[sb] = h0; Ah[sb + 1] = h1;
        Al[sb] = l0; Al[sb + 1] = l1;
    }
    __syncthreads();

    // ---- MMA: warp (wr, wc): rows wr*32..+31, cols wc*32..+31 ----
    const int wid = tid >> 5, lane = tid & 31;
    const int gid = lane >> 2, tig = lane & 3;
    const int wr = wid & 1, wc = wid >> 1;
    const int ar0 = wr * 32, cn0 = wc * 32;

    float acc[2][4][4];
#pragma unroll
    for (int mt = 0; mt < 2; ++mt)
#pragma unroll
        for (int nt = 0; nt < 4; ++nt)
#pragma unroll
            for (int j = 0; j < 4; ++j) acc[mt][nt][j] = 0.f;

#pragma unroll
    for (int ks = 0; ks < 8; ++ks) {          // K = 8 steps * 16
        const int k0w = ks * 8;               // word offset (bf16x2)
        uint32_t ah[2][4], al[2][4];
#pragma unroll
        for (int mt = 0; mt < 2; ++mt) {
            int base = (ar0 + mt * 16 + gid) * STR + k0w + tig;
            ah[mt][0] = Ah[base];
            ah[mt][1] = Ah[base + 8 * STR];
            ah[mt][2] = Ah[base + 4];
            ah[mt][3] = Ah[base + 8 * STR + 4];
            al[mt][0] = Al[base];
            al[mt][1] = Al[base + 8 * STR];
            al[mt][2] = Al[base + 4];
            al[mt][3] = Al[base + 8 * STR + 4];
        }
#pragma unroll
        for (int nt = 0; nt < 4; ++nt) {
            int nb = (cn0 + nt * 8 + gid) * STR + k0w + tig;
            uint32_t bh0 = Wsh[nb], bh1 = Wsh[nb + 4];
            uint32_t bl0 = Wsl[nb], bl1 = Wsl[nb + 4];
            // hi*hi + lo*hi + hi*lo  (3xBF16)
            mma16(acc[0][nt], ah[0], bh0, bh1);
            mma16(acc[1][nt], ah[1], bh0, bh1);
            mma16(acc[0][nt], al[0], bh0, bh1);
            mma16(acc[1][nt], al[1], bh0, bh1);
            mma16(acc[0][nt], ah[0], bl0, bl1);
            mma16(acc[1][nt], ah[1], bl0, bl1);
        }
    }

    // ---- epilogue ----
#pragma unroll
    for (int mt = 0; mt < 2; ++mt) {
#pragma unroll
        for (int half = 0; half < 2; ++half) {
            const int r  = r0 + ar0 + mt * 16 + gid + half * 8;
            const int sc = __ldg(&scat[r]);
            float* ap = Acc + (size_t)sc * EH;
#pragma unroll
            for (int nt = 0; nt < 4; ++nt) {
                const int col = cn0 + nt * 8 + tig * 2;
                float x = acc[mt][nt][half * 2 + 0];
                float y = acc[mt][nt][half * 2 + 1];
                if constexpr (OUT) {
                    x += obias[col]; y += obias[col + 1];
                } else {
                    uint32_t hw, lw;
                    split2(x, y, hw, lw);
                    size_t gw = (size_t)r * 64 + (col >> 1);
                    Goh[gw] = hw; Gol[gw] = lw;
                }
                red2(ap + col, x, y);
            }
        }
    }
}

// ============================================================
// Scalar fp32 GEMM (precompute GEMMs)
// EPI 0: C = acc + bias (fp32 store)
// EPI 1: packed hi/lo store of acc + bias + gadd[gidx[row]]
// ============================================================
template <int KTOT, int EPI>
__global__ void __launch_bounds__(256)
gemm_tile(const float* __restrict__ A, const float* __restrict__ W,
          const float* __restrict__ bias, float* __restrict__ C, int M,
          const int* __restrict__ gidx, const float* __restrict__ gadd,
          uint32_t* __restrict__ Ch, uint32_t* __restrict__ Cl)
{
    constexpr int KC = (KTOT < 32) ? KTOT : 32;
    __shared__ float As[KC][132];
    __shared__ float Ws[KC][128];

    const int tid = threadIdx.x;
    const int tr  = tid >> 4;
    const int tc  = tid & 15;
    const int r0  = blockIdx.x * 128;

    float acc[8][8];
#pragma unroll
    for (int i = 0; i < 8; ++i)
#pragma unroll
        for (int j = 0; j < 8; ++j) acc[i][j] = 0.f;

    for (int kc0 = 0; kc0 < KTOT; kc0 += KC) {
        __syncthreads();
#pragma unroll
        for (int i = 0; i < KC / 8; ++i) {
            int f  = tid + i * 256;
            int r  = f / (KC / 4);
            int c4 = (f % (KC / 4)) * 4;
            float4 v = make_float4(0.f, 0.f, 0.f, 0.f);
            int gr = r0 + r;
            if (gr < M) v = *(const float4*)(A + (size_t)gr * KTOT + kc0 + c4);
            As[c4 + 0][r] = v.x; As[c4 + 1][r] = v.y;
            As[c4 + 2][r] = v.z; As[c4 + 3][r] = v.w;
        }
#pragma unroll
        for (int i = 0; i < KC / 8; ++i) {
            int f  = tid + i * 256;
            int kr = f >> 5;
            int c4 = (f & 31) * 4;
            *(float4*)(&Ws[kr][c4]) = *(const float4*)(W + (size_t)(kc0 + kr) * EH + c4);
        }
        __syncthreads();
#pragma unroll
        for (int k = 0; k < KC; ++k) {
            float a[8], w[8];
            *(float4*)&a[0] = *(const float4*)&As[k][tr * 8];
            *(float4*)&a[4] = *(const float4*)&As[k][tr * 8 + 4];
            *(float4*)&w[0] = *(const float4*)&Ws[k][tc * 8];
            *(float4*)&w[4] = *(const float4*)&Ws[k][tc * 8 + 4];
#pragma unroll
            for (int i = 0; i < 8; ++i)
#pragma unroll
                for (int j = 0; j < 8; ++j) acc[i][j] += a[i] * w[j];
        }
    }

    float bs[8];
#pragma unroll
    for (int j = 0; j < 8; ++j) bs[j] = bias[tc * 8 + j];

    const int c0 = tc * 8;
#pragma unroll
    for (int i = 0; i < 8; ++i) {
        int r = r0 + tr * 8 + i;
        if (r >= M) continue;
        if constexpr (EPI == 0) {
            float4 v0, v1;
            v0.x = acc[i][0] + bs[0]; v0.y = acc[i][1] + bs[1];
            v0.z = acc[i][2] + bs[2]; v0.w = acc[i][3] + bs[3];
            v1.x = acc[i][4] + bs[4]; v1.y = acc[i][5] + bs[5];
            v1.z = acc[i][6] + bs[6]; v1.w = acc[i][7] + bs[7];
            *(float4*)(C + (size_t)r * EH + c0)     = v0;
            *(float4*)(C + (size_t)r * EH + c0 + 4) = v1;
        } else {
            int u = gidx[r];
            const float* gp = gadd + (size_t)u * EH + c0;
            float4 p0 = *(const float4*)gp;
            float4 p1 = *(const float4*)(gp + 4);
            float vals[8];
            vals[0] = acc[i][0] + bs[0] + p0.x; vals[1] = acc[i][1] + bs[1] + p0.y;
            vals[2] = acc[i][2] + bs[2] + p0.z; vals[3] = acc[i][3] + bs[3] + p0.w;
            vals[4] = acc[i][4] + bs[4] + p1.x; vals[5] = acc[i][5] + bs[5] + p1.y;
            vals[6] = acc[i][6] + bs[6] + p1.z; vals[7] = acc[i][7] + bs[7] + p1.w;
            size_t base = ((size_t)r * EH + c0) >> 1;
            uint32_t hw[4], lw[4];
#pragma unroll
            for (int p = 0; p < 4; ++p)
                split2(vals[2 * p], vals[2 * p + 1], hw[p], lw[p]);
            *(uint4*)(Ch + base) = make_uint4(hw[0], hw[1], hw[2], hw[3]);
            *(uint4*)(Cl + base) = make_uint4(lw[0], lw[1], lw[2], lw[3]);
        }
    }
}

// out = relu(out + U1x)
__global__ void __launch_bounds__(256)
final_relu(float* __restrict__ out, const float* __restrict__ U1x)
{
    int idx = blockIdx.x * blockDim.x + threadIdx.x;
    if (idx >= NN * EH / 4) return;
    float4 a = ((const float4*)out)[idx];
    float4 b = ((const float4*)U1x)[idx];
    float4 r;
    r.x = fmaxf(a.x + b.x, 0.f);
    r.y = fmaxf(a.y + b.y, 0.f);
    r.z = fmaxf(a.z + b.z, 0.f);
    r.w = fmaxf(a.w + b.w, 0.f);
    ((float4*)out)[idx] = r;
}

extern "C" void kernel_launch(void* const* d_in, const int* in_sizes, int n_in,
                              void* d_out, int out_size)
{
    const float* nf  = (const float*)d_in[0];
    const float* ef  = (const float*)d_in[1];
    const int*   edg = (const int*)  d_in[3];
    const float* W1w = (const float*)d_in[4];
    const float* W1b = (const float*)d_in[5];
    const float* W2w = (const float*)d_in[6];
    const float* W2b = (const float*)d_in[7];
    const float* W3w = (const float*)d_in[8];
    const float* W3b = (const float*)d_in[9];
    const float* U1w = (const float*)d_in[10];
    const float* U1b = (const float*)d_in[11];
    const float* U2w = (const float*)d_in[12];
    const float* U2b = (const float*)d_in[13];

    const int* from = edg;
    const int* to   = edg + NE;

    float *P, *U1x, *T0, *T1, *cb;
    uint32_t *Bh, *Bl, *Gh0, *Gl0, *Gh1, *Gl1, *W3h, *W3l, *U2h, *U2l;
    cudaGetSymbolAddress((void**)&P,   g_P);
    cudaGetSymbolAddress((void**)&U1x, g_U1);
    cudaGetSymbolAddress((void**)&Bh,  g_Bh);
    cudaGetSymbolAddress((void**)&Bl,  g_Bl);
    cudaGetSymbolAddress((void**)&Gh0, g_Gh0);
    cudaGetSymbolAddress((void**)&Gl0, g_Gl0);
    cudaGetSymbolAddress((void**)&Gh1, g_Gh1);
    cudaGetSymbolAddress((void**)&Gl1, g_Gl1);
    cudaGetSymbolAddress((void**)&T0,  g_T0);
    cudaGetSymbolAddress((void**)&T1,  g_T1);
    cudaGetSymbolAddress((void**)&W3h, g_W3h);
    cudaGetSymbolAddress((void**)&W3l, g_W3l);
    cudaGetSymbolAddress((void**)&U2h, g_U2h);
    cudaGetSymbolAddress((void**)&U2l, g_U2l);
    cudaGetSymbolAddress((void**)&cb,  g_cb);

    cudaFuncSetAttribute(gemm_fused<true,  false>,
                         cudaFuncAttributeMaxDynamicSharedMemorySize, (int)SM_TOT);
    cudaFuncSetAttribute(gemm_fused<false, false>,
                         cudaFuncAttributeMaxDynamicSharedMemorySize, (int)SM_TOT);
    cudaFuncSetAttribute(gemm_fused<false, true>,
                         cudaFuncAttributeMaxDynamicSharedMemorySize, (int)SM_TOT);

    const int gnode = (NN + 127) / 128;
    const int gedge128 = (NE + 127) / 128;
    const int gedge64  = NE / 64;          // 9375, exact

    // weight prep + combined bias (single launch)
    prep_all<<<65, 256>>>(W3w, U2w, W2b, W3b, W3h, W3l, U2h, U2l, cb);

    // loop-invariant precomputes
    gemm_tile<64, 0><<<gnode, 256>>>(nf, W1w, W1b, P,   NN, nullptr, nullptr,
                                     nullptr, nullptr);
    gemm_tile<64, 0><<<gnode, 256>>>(nf, U1w, U1b, U1x, NN, nullptr, nullptr,
                                     nullptr, nullptr);
    gemm_tile<16, 1><<<gedge128, 256>>>(ef, W2w, cb, nullptr, NE, from, P, Bh, Bl);

    // buffers: step s output lives in buffer (s & 1)
    uint32_t* Ghb[2] = {Gh0, Gh1};
    uint32_t* Glb[2] = {Gl0, Gl1};
    float*    Tb [2] = {T0, T1};

    // s = 1: h1 = relu(B'), G = h1@W3, T = seg(G, from)  -> buffer 1
    cudaMemsetAsync(Tb[1], 0, (size_t)NN * EH * sizeof(float));
    gemm_fused<true, false><<<gedge64, 256, SM_TOT>>>(
        Bh, Bl, nullptr, nullptr, nullptr, W3h, W3l, from, from, nullptr,
        Ghb[1], Glb[1], Tb[1]);

    // s = 2..5: read buffer (s-1)&1, write buffer s&1
    for (int s = 2; s <= 5; ++s) {
        cudaMemsetAsync(Tb[s & 1], 0, (size_t)NN * EH * sizeof(float));
        gemm_fused<false, false><<<gedge64, 256, SM_TOT>>>(
            Bh, Bl, Tb[(s - 1) & 1], Ghb[(s - 1) & 1], Glb[(s - 1) & 1],
            W3h, W3l, from, from, nullptr, Ghb[s & 1], Glb[s & 1], Tb[s & 1]);
    }

    // readout: h6 built on the fly from (T5, G5) = buffer 1; red into d_out by `to`
    cudaMemsetAsync(d_out, 0, (size_t)NN * EH * sizeof(float));
    gemm_fused<false, true><<<gedge64, 256, SM_TOT>>>(
        Bh, Bl, Tb[1], Ghb[1], Glb[1], U2h, U2l, from, to, U2b,
        nullptr, nullptr, (float*)d_out);

    final_relu<<<(NN * EH / 4 + 255) / 256, 256>>>((float*)d_out, U1x);
}

// round 8
// speedup vs baseline: 1.0899x; 1.0899x over previous
#include <cuda_runtime.h>
#include <cuda_bf16.h>
#include <cstdint>
#include <cstddef>

#define NN 100000
#define NE 600000
#define NF 64
#define EF 16
#define EH 128
#define NSTEPS 6
#define NTILE (NE / 64)      // 9375
#define NBLK  296            // 2 CTAs x 148 SMs, persistent

// ---- scratch (device globals; no allocation allowed) ----
__device__ float    g_P  [(size_t)NN * EH];   // nf@W1 + b1
__device__ float    g_U1 [(size_t)NN * EH];   // nf@U1 + b1
__device__ float    g_B  [(size_t)NE * EH];   // B' = P[from] + ef@W2 + b2 + b3
__device__ float    g_G0 [(size_t)NE * EH];   // G ping
__device__ float    g_G1 [(size_t)NE * EH];   // G pong
__device__ float    g_T0 [(size_t)NN * EH];   // T ping
__device__ float    g_T1 [(size_t)NN * EH];   // T pong
__device__ uint32_t g_W3h[128 * 64];          // W3^T hi, bf16x2 packed along k
__device__ uint32_t g_W3l[128 * 64];          // W3^T lo
__device__ uint32_t g_U2h[128 * 64];          // U2^T hi
__device__ uint32_t g_U2l[128 * 64];          // U2^T lo
__device__ float    g_cb [EH];                // W2_b + W3_b

// ================= helpers =================
__device__ __forceinline__ void mma16(float* c, const uint32_t* a,
                                      uint32_t b0, uint32_t b1) {
    asm volatile(
        "mma.sync.aligned.m16n8k16.row.col.f32.bf16.bf16.f32 "
        "{%0,%1,%2,%3}, {%4,%5,%6,%7}, {%8,%9}, {%0,%1,%2,%3};"
        : "+f"(c[0]), "+f"(c[1]), "+f"(c[2]), "+f"(c[3])
        : "r"(a[0]), "r"(a[1]), "r"(a[2]), "r"(a[3]), "r"(b0), "r"(b1));
}

__device__ __forceinline__ void red2(float* p, float x, float y) {
    asm volatile("red.global.add.v2.f32 [%0], {%1, %2};"
                 :: "l"(p), "f"(x), "f"(y) : "memory");
}

// split fp32 pair into bf16x2 hi + bf16x2 lo (packed 32-bit words)
__device__ __forceinline__ void split2(float x, float y, uint32_t& hi, uint32_t& lo) {
    __nv_bfloat162 h = __floats2bfloat162_rn(x, y);
    float2 hf = __bfloat1622float2(h);
    __nv_bfloat162 l = __floats2bfloat162_rn(x - hf.x, y - hf.y);
    hi = *(uint32_t*)&h;
    lo = *(uint32_t*)&l;
}

// one launch: pack W3^T, U2^T (hi/lo), and combined bias
__global__ void prep_all(const float* __restrict__ W3, const float* __restrict__ U2,
                         const float* __restrict__ W2b, const float* __restrict__ W3b,
                         uint32_t* __restrict__ W3h, uint32_t* __restrict__ W3l,
                         uint32_t* __restrict__ U2h, uint32_t* __restrict__ U2l,
                         float* __restrict__ cb) {
    int b = blockIdx.x, tid = threadIdx.x;
    if (b < 64) {
        const float* W = (b < 32) ? W3 : U2;
        uint32_t* oh = (b < 32) ? W3h : U2h;
        uint32_t* ol = (b < 32) ? W3l : U2l;
        int idx = (b & 31) * 256 + tid;          // 0..8191
        int n = idx >> 6, kp = idx & 63;
        float v0 = W[(kp * 2 + 0) * 128 + n];
        float v1 = W[(kp * 2 + 1) * 128 + n];
        uint32_t hi, lo;
        split2(v0, v1, hi, lo);
        oh[idx] = hi; ol[idx] = lo;
    } else {
        if (tid < EH) cb[tid] = W2b[tid] + W3b[tid];
    }
}

// ============================================================
// Fused 3xBF16 MMA GEMM over edges — PERSISTENT version.
// 296 CTAs; each stages W once, then grid-strides over 64-row tiles.
// A row e built on the fly:
//   FIRST:  a = relu(Bp[e])
//   else :  a = relu(Bp[e] + Tprev[from[e]] - Gprev[e^1])
// Epilogue:
//   STEP (!OUT): Gout[e] = acc ; red.v2 Acc[from[e]] += acc
//   OUT        : red.v2 Acc[to[e]] += acc + obias
// ============================================================
static constexpr int STR = 68;                        // words (bf16x2) per row, padded
static constexpr int OFF_AH = 0;                      // [64][68]
static constexpr int OFF_AL = 64 * STR;
static constexpr int OFF_WH = 2 * 64 * STR;           // [128][68]
static constexpr int OFF_WL = 2 * 64 * STR + 128 * STR;
static constexpr int SM_WORDS = OFF_WL + 128 * STR;
static constexpr size_t SM_TOT = (size_t)SM_WORDS * 4;  // 104448 B

template <bool FIRST, bool OUT>
__global__ void __launch_bounds__(256, 2)
gemm_fused(const float* __restrict__ Bp, const float* __restrict__ Tprev,
           const float* __restrict__ Gprev,
           const uint32_t* __restrict__ Wh, const uint32_t* __restrict__ Wl,
           const int* __restrict__ from, const int* __restrict__ scat,
           const float* __restrict__ obias,
           float* __restrict__ Gout, float* __restrict__ Acc)
{
    extern __shared__ uint32_t smem[];
    uint32_t* Ah  = smem + OFF_AH;
    uint32_t* Al  = smem + OFF_AL;
    uint32_t* Wsh = smem + OFF_WH;
    uint32_t* Wsl = smem + OFF_WL;

    const int tid = threadIdx.x;

    // ---- stage W hi/lo ONCE ----
#pragma unroll
    for (int i = 0; i < 8; ++i) {
        int f = tid + i * 256;               // 0..2047 uint4s over 8192 words
        int n = f >> 4, c = (f & 15) * 4;
        uint4 vh = *(const uint4*)(Wh + n * 64 + c);
        uint4 vl = *(const uint4*)(Wl + n * 64 + c);
        *(uint4*)(Wsh + n * STR + c) = vh;
        *(uint4*)(Wsl + n * STR + c) = vl;
    }

    const int wid = tid >> 5, lane = tid & 31;
    const int gid = lane >> 2, tig = lane & 3;
    const int wr = wid & 1, wc = wid >> 1;
    const int ar0 = wr * 32, cn0 = wc * 32;

    float obv[8];
    if constexpr (OUT) {
#pragma unroll
        for (int nt = 0; nt < 4; ++nt) {
            obv[2 * nt]     = obias[cn0 + nt * 8 + tig * 2];
            obv[2 * nt + 1] = obias[cn0 + nt * 8 + tig * 2 + 1];
        }
    }

    for (int t = blockIdx.x; t < NTILE; t += NBLK) {
        const int r0 = t * 64;
        __syncthreads();   // previous iteration's MMA reads done (also no-op cost at t0)

        // ---- stage A with fused combine + bf16 split ----
#pragma unroll
        for (int i = 0; i < 8; ++i) {
            int f   = tid + i * 256;             // 0..2047 float4s
            int row = f >> 5, c4 = (f & 31) * 4; // float col
            int e   = r0 + row;
            float4 b = *(const float4*)(Bp + (size_t)e * EH + c4);
            float4 v;
            if constexpr (FIRST) {
                v.x = fmaxf(b.x, 0.f); v.y = fmaxf(b.y, 0.f);
                v.z = fmaxf(b.z, 0.f); v.w = fmaxf(b.w, 0.f);
            } else {
                int u = __ldg(&from[e]);
                float4 tt = *(const float4*)(Tprev + (size_t)u * EH + c4);
                float4 g  = *(const float4*)(Gprev + (size_t)(e ^ 1) * EH + c4);
                v.x = fmaxf(b.x + tt.x - g.x, 0.f);
                v.y = fmaxf(b.y + tt.y - g.y, 0.f);
                v.z = fmaxf(b.z + tt.z - g.z, 0.f);
                v.w = fmaxf(b.w + tt.w - g.w, 0.f);
            }
            uint32_t h0, l0, h1, l1;
            split2(v.x, v.y, h0, l0);
            split2(v.z, v.w, h1, l1);
            int wb = row * STR + (c4 >> 1);
            Ah[wb] = h0; Ah[wb + 1] = h1;
            Al[wb] = l0; Al[wb + 1] = l1;
        }
        __syncthreads();

        // ---- MMA ----
        float acc[2][4][4];
#pragma unroll
        for (int mt = 0; mt < 2; ++mt)
#pragma unroll
            for (int nt = 0; nt < 4; ++nt)
#pragma unroll
                for (int j = 0; j < 4; ++j) acc[mt][nt][j] = 0.f;

#pragma unroll
        for (int ks = 0; ks < 8; ++ks) {          // K = 8 steps * 16
            const int k0w = ks * 8;
            uint32_t ah[2][4], al[2][4];
#pragma unroll
            for (int mt = 0; mt < 2; ++mt) {
                int base = (ar0 + mt * 16 + gid) * STR + k0w + tig;
                ah[mt][0] = Ah[base];
                ah[mt][1] = Ah[base + 8 * STR];
                ah[mt][2] = Ah[base + 4];
                ah[mt][3] = Ah[base + 8 * STR + 4];
                al[mt][0] = Al[base];
                al[mt][1] = Al[base + 8 * STR];
                al[mt][2] = Al[base + 4];
                al[mt][3] = Al[base + 8 * STR + 4];
            }
#pragma unroll
            for (int nt = 0; nt < 4; ++nt) {
                int nb = (cn0 + nt * 8 + gid) * STR + k0w + tig;
                uint32_t bh0 = Wsh[nb], bh1 = Wsh[nb + 4];
                uint32_t bl0 = Wsl[nb], bl1 = Wsl[nb + 4];
                // hi*hi + lo*hi + hi*lo  (3xBF16)
                mma16(acc[0][nt], ah[0], bh0, bh1);
                mma16(acc[1][nt], ah[1], bh0, bh1);
                mma16(acc[0][nt], al[0], bh0, bh1);
                mma16(acc[1][nt], al[1], bh0, bh1);
                mma16(acc[0][nt], ah[0], bl0, bl1);
                mma16(acc[1][nt], ah[1], bl0, bl1);
            }
        }

        // ---- epilogue (gmem only) ----
#pragma unroll
        for (int mt = 0; mt < 2; ++mt) {
#pragma unroll
            for (int half = 0; half < 2; ++half) {
                const int r  = r0 + ar0 + mt * 16 + gid + half * 8;
                const int sc = __ldg(&scat[r]);
                float* ap = Acc + (size_t)sc * EH;
#pragma unroll
                for (int nt = 0; nt < 4; ++nt) {
                    const int col = cn0 + nt * 8 + tig * 2;
                    float x = acc[mt][nt][half * 2 + 0];
                    float y = acc[mt][nt][half * 2 + 1];
                    if constexpr (OUT) {
                        x += obv[2 * nt]; y += obv[2 * nt + 1];
                    } else {
                        *(float2*)(Gout + (size_t)r * EH + col) = make_float2(x, y);
                    }
                    red2(ap + col, x, y);
                }
            }
        }
    }
}

// ============================================================
// Scalar fp32 GEMM (small precompute GEMMs only)
// EPI 0: C = acc + bias ; EPI 1: C = acc + bias + gadd[gidx[row]]
// ============================================================
template <int KTOT, int EPI>
__global__ void __launch_bounds__(256)
gemm_tile(const float* __restrict__ A, const float* __restrict__ W,
          const float* __restrict__ bias, float* __restrict__ C, int M,
          const int* __restrict__ gidx, const float* __restrict__ gadd)
{
    constexpr int KC = (KTOT < 32) ? KTOT : 32;
    __shared__ float As[KC][132];
    __shared__ float Ws[KC][128];

    const int tid = threadIdx.x;
    const int tr  = tid >> 4;
    const int tc  = tid & 15;
    const int r0  = blockIdx.x * 128;

    float acc[8][8];
#pragma unroll
    for (int i = 0; i < 8; ++i)
#pragma unroll
        for (int j = 0; j < 8; ++j) acc[i][j] = 0.f;

    for (int kc0 = 0; kc0 < KTOT; kc0 += KC) {
        __syncthreads();
#pragma unroll
        for (int i = 0; i < KC / 8; ++i) {
            int f  = tid + i * 256;
            int r  = f / (KC / 4);
            int c4 = (f % (KC / 4)) * 4;
            float4 v = make_float4(0.f, 0.f, 0.f, 0.f);
            int gr = r0 + r;
            if (gr < M) v = *(const float4*)(A + (size_t)gr * KTOT + kc0 + c4);
            As[c4 + 0][r] = v.x; As[c4 + 1][r] = v.y;
            As[c4 + 2][r] = v.z; As[c4 + 3][r] = v.w;
        }
#pragma unroll
        for (int i = 0; i < KC / 8; ++i) {
            int f  = tid + i * 256;
            int kr = f >> 5;
            int c4 = (f & 31) * 4;
            *(float4*)(&Ws[kr][c4]) = *(const float4*)(W + (size_t)(kc0 + kr) * EH + c4);
        }
        __syncthreads();
#pragma unroll
        for (int k = 0; k < KC; ++k) {
            float a[8], w[8];
            *(float4*)&a[0] = *(const float4*)&As[k][tr * 8];
            *(float4*)&a[4] = *(const float4*)&As[k][tr * 8 + 4];
            *(float4*)&w[0] = *(const float4*)&Ws[k][tc * 8];
            *(float4*)&w[4] = *(const float4*)&Ws[k][tc * 8 + 4];
#pragma unroll
            for (int i = 0; i < 8; ++i)
#pragma unroll
                for (int j = 0; j < 8; ++j) acc[i][j] += a[i] * w[j];
        }
    }

    float bs[8];
#pragma unroll
    for (int j = 0; j < 8; ++j) bs[j] = bias[tc * 8 + j];

    const int c0 = tc * 8;
#pragma unroll
    for (int i = 0; i < 8; ++i) {
        int r = r0 + tr * 8 + i;
        if (r >= M) continue;
        if constexpr (EPI == 0) {
            float4 v0, v1;
            v0.x = acc[i][0] + bs[0]; v0.y = acc[i][1] + bs[1];
            v0.z = acc[i][2] + bs[2]; v0.w = acc[i][3] + bs[3];
            v1.x = acc[i][4] + bs[4]; v1.y = acc[i][5] + bs[5];
            v1.z = acc[i][6] + bs[6]; v1.w = acc[i][7] + bs[7];
            *(float4*)(C + (size_t)r * EH + c0)     = v0;
            *(float4*)(C + (size_t)r * EH + c0 + 4) = v1;
        } else {
            int u = gidx[r];
            const float* gp = gadd + (size_t)u * EH + c0;
            float4 p0 = *(const float4*)gp;
            float4 p1 = *(const float4*)(gp + 4);
            float4 v0, v1;
            v0.x = acc[i][0] + bs[0] + p0.x; v0.y = acc[i][1] + bs[1] + p0.y;
            v0.z = acc[i][2] + bs[2] + p0.z; v0.w = acc[i][3] + bs[3] + p0.w;
            v1.x = acc[i][4] + bs[4] + p1.x; v1.y = acc[i][5] + bs[5] + p1.y;
            v1.z = acc[i][6] + bs[6] + p1.z; v1.w = acc[i][7] + bs[7] + p1.w;
            *(float4*)(C + (size_t)r * EH + c0)     = v0;
            *(float4*)(C + (size_t)r * EH + c0 + 4) = v1;
        }
    }
}

// out = relu(out + U1x)
__global__ void __launch_bounds__(256)
final_relu(float* __restrict__ out, const float* __restrict__ U1x)
{
    int idx = blockIdx.x * blockDim.x + threadIdx.x;
    if (idx >= NN * EH / 4) return;
    float4 a = ((const float4*)out)[idx];
    float4 b = ((const float4*)U1x)[idx];
    float4 r;
    r.x = fmaxf(a.x + b.x, 0.f);
    r.y = fmaxf(a.y + b.y, 0.f);
    r.z = fmaxf(a.z + b.z, 0.f);
    r.w = fmaxf(a.w + b.w, 0.f);
    ((float4*)out)[idx] = r;
}

extern "C" void kernel_launch(void* const* d_in, const int* in_sizes, int n_in,
                              void* d_out, int out_size)
{
    const float* nf  = (const float*)d_in[0];
    const float* ef  = (const float*)d_in[1];
    const int*   edg = (const int*)  d_in[3];
    const float* W1w = (const float*)d_in[4];
    const float* W1b = (const float*)d_in[5];
    const float* W2w = (const float*)d_in[6];
    const float* W2b = (const float*)d_in[7];
    const float* W3w = (const float*)d_in[8];
    const float* W3b = (const float*)d_in[9];
    const float* U1w = (const float*)d_in[10];
    const float* U1b = (const float*)d_in[11];
    const float* U2w = (const float*)d_in[12];
    const float* U2b = (const float*)d_in[13];

    const int* from = edg;
    const int* to   = edg + NE;

    float *P, *U1x, *B, *G0, *G1, *T0, *T1, *cb;
    uint32_t *W3h, *W3l, *U2h, *U2l;
    cudaGetSymbolAddress((void**)&P,   g_P);
    cudaGetSymbolAddress((void**)&U1x, g_U1);
    cudaGetSymbolAddress((void**)&B,   g_B);
    cudaGetSymbolAddress((void**)&G0,  g_G0);
    cudaGetSymbolAddress((void**)&G1,  g_G1);
    cudaGetSymbolAddress((void**)&T0,  g_T0);
    cudaGetSymbolAddress((void**)&T1,  g_T1);
    cudaGetSymbolAddress((void**)&W3h, g_W3h);
    cudaGetSymbolAddress((void**)&W3l, g_W3l);
    cudaGetSymbolAddress((void**)&U2h, g_U2h);
    cudaGetSymbolAddress((void**)&U2l, g_U2l);
    cudaGetSymbolAddress((void**)&cb,  g_cb);

    cudaFuncSetAttribute(gemm_fused<true,  false>,
                         cudaFuncAttributeMaxDynamicSharedMemorySize, (int)SM_TOT);
    cudaFuncSetAttribute(gemm_fused<false, false>,
                         cudaFuncAttributeMaxDynamicSharedMemorySize, (int)SM_TOT);
    cudaFuncSetAttribute(gemm_fused<false, true>,
                         cudaFuncAttributeMaxDynamicSharedMemorySize, (int)SM_TOT);

    const int gnode = (NN + 127) / 128;
    const int gedge128 = (NE + 127) / 128;

    // weight prep + combined bias (single launch)
    prep_all<<<65, 256>>>(W3w, U2w, W2b, W3b, W3h, W3l, U2h, U2l, cb);

    // loop-invariant precomputes
    gemm_tile<64, 0><<<gnode, 256>>>(nf, W1w, W1b, P,   NN, nullptr, nullptr);
    gemm_tile<64, 0><<<gnode, 256>>>(nf, U1w, U1b, U1x, NN, nullptr, nullptr);
    gemm_tile<16, 1><<<gedge128, 256>>>(ef, W2w, cb, B, NE, from, P);

    // buffers: step s output lives in buffer (s & 1)
    float* Gb[2] = {G0, G1};
    float* Tb[2] = {T0, T1};

    // s = 1: h1 = relu(B'), G = h1@W3, T = seg(G, from)  -> buffer 1
    cudaMemsetAsync(Tb[1], 0, (size_t)NN * EH * sizeof(float));
    gemm_fused<true, false><<<NBLK, 256, SM_TOT>>>(
        B, nullptr, nullptr, W3h, W3l, from, from, nullptr, Gb[1], Tb[1]);

    // s = 2..5: read buffer (s-1)&1, write buffer s&1
    for (int s = 2; s <= 5; ++s) {
        cudaMemsetAsync(Tb[s & 1], 0, (size_t)NN * EH * sizeof(float));
        gemm_fused<false, false><<<NBLK, 256, SM_TOT>>>(
            B, Tb[(s - 1) & 1], Gb[(s - 1) & 1], W3h, W3l, from, from, nullptr,
            Gb[s & 1], Tb[s & 1]);
    }

    // readout: h6 built on the fly from (T5, G5) = buffer 1; red into d_out by `to`
    cudaMemsetAsync(d_out, 0, (size_t)NN * EH * sizeof(float));
    gemm_fused<false, true><<<NBLK, 256, SM_TOT>>>(
        B, Tb[1], Gb[1], U2h, U2l, from, to, U2b, nullptr, (float*)d_out);

    final_relu<<<(NN * EH / 4 + 255) / 256, 256>>>((float*)d_out, U1x);
}

// round 9
// speedup vs baseline: 1.0974x; 1.0069x over previous
#include <cuda_runtime.h>
#include <cuda_bf16.h>
#include <cstdint>
#include <cstddef>

#define NN 100000
#define NE 600000
#define NF 64
#define EF 16
#define EH 128
#define NSTEPS 6
#define NTILE (NE / 64)      // 9375
#define NBLK  296            // 2 CTAs x 148 SMs, persistent

// ---- scratch (device globals; no allocation allowed) ----
__device__ float    g_P  [(size_t)NN * EH];   // nf@W1 + b1
__device__ float    g_U1 [(size_t)NN * EH];   // nf@U1 + b1
__device__ float    g_B  [(size_t)NE * EH];   // B' = P[from] + ef@W2 + b2 + b3
__device__ float    g_G0 [(size_t)NE * EH];   // G ping
__device__ float    g_G1 [(size_t)NE * EH];   // G pong
__device__ float    g_T0 [(size_t)NN * EH];   // T ping
__device__ float    g_T1 [(size_t)NN * EH];   // T pong
__device__ uint32_t g_W3h[128 * 64];          // W3^T hi, bf16x2 packed along k
__device__ uint32_t g_W3l[128 * 64];          // W3^T lo
__device__ uint32_t g_U2h[128 * 64];          // U2^T hi
__device__ uint32_t g_U2l[128 * 64];          // U2^T lo
__device__ float    g_cb [EH];                // W2_b + W3_b

// ================= helpers =================
__device__ __forceinline__ void mma16(float* c, const uint32_t* a,
                                      uint32_t b0, uint32_t b1) {
    asm volatile(
        "mma.sync.aligned.m16n8k16.row.col.f32.bf16.bf16.f32 "
        "{%0,%1,%2,%3}, {%4,%5,%6,%7}, {%8,%9}, {%0,%1,%2,%3};"
        : "+f"(c[0]), "+f"(c[1]), "+f"(c[2]), "+f"(c[3])
        : "r"(a[0]), "r"(a[1]), "r"(a[2]), "r"(a[3]), "r"(b0), "r"(b1));
}

__device__ __forceinline__ void red2(float* p, float x, float y) {
    asm volatile("red.global.add.v2.f32 [%0], {%1, %2};"
                 :: "l"(p), "f"(x), "f"(y) : "memory");
}

// split fp32 pair into bf16x2 hi + bf16x2 lo (packed 32-bit words)
__device__ __forceinline__ void split2(float x, float y, uint32_t& hi, uint32_t& lo) {
    __nv_bfloat162 h = __floats2bfloat162_rn(x, y);
    float2 hf = __bfloat1622float2(h);
    __nv_bfloat162 l = __floats2bfloat162_rn(x - hf.x, y - hf.y);
    hi = *(uint32_t*)&h;
    lo = *(uint32_t*)&l;
}

// one launch: pack W3^T, U2^T (hi/lo), and combined bias
__global__ void prep_all(const float* __restrict__ W3, const float* __restrict__ U2,
                         const float* __restrict__ W2b, const float* __restrict__ W3b,
                         uint32_t* __restrict__ W3h, uint32_t* __restrict__ W3l,
                         uint32_t* __restrict__ U2h, uint32_t* __restrict__ U2l,
                         float* __restrict__ cb) {
    int b = blockIdx.x, tid = threadIdx.x;
    if (b < 64) {
        const float* W = (b < 32) ? W3 : U2;
        uint32_t* oh = (b < 32) ? W3h : U2h;
        uint32_t* ol = (b < 32) ? W3l : U2l;
        int idx = (b & 31) * 256 + tid;          // 0..8191
        int n = idx >> 6, kp = idx & 63;
        float v0 = W[(kp * 2 + 0) * 128 + n];
        float v1 = W[(kp * 2 + 1) * 128 + n];
        uint32_t hi, lo;
        split2(v0, v1, hi, lo);
        oh[idx] = hi; ol[idx] = lo;
    } else {
        if (tid < EH) cb[tid] = W2b[tid] + W3b[tid];
    }
}

// ============================================================
// Fused 3xBF16 MMA GEMM over edges — PERSISTENT version.
// 296 CTAs; each stages W once, then grid-strides over 64-row tiles.
// A row e built on the fly:
//   FIRST:  a = relu(Bp[e])
//   else :  a = relu(Bp[e] + Tprev[from[e]] - Gprev[e^1])
// Epilogue:
//   STEP (!OUT): Gout[e] = acc ; red.v2 Acc[from[e]] += acc
//   OUT        : red.v2 Acc[to[e]] += acc + obias
// ============================================================
static constexpr int STR = 68;                        // words (bf16x2) per row, padded
static constexpr int OFF_AH = 0;                      // [64][68]
static constexpr int OFF_AL = 64 * STR;
static constexpr int OFF_WH = 2 * 64 * STR;           // [128][68]
static constexpr int OFF_WL = 2 * 64 * STR + 128 * STR;
static constexpr int SM_WORDS = OFF_WL + 128 * STR;
static constexpr size_t SM_TOT = (size_t)SM_WORDS * 4;  // 104448 B

template <bool FIRST, bool OUT>
__global__ void __launch_bounds__(256, 2)
gemm_fused(const float* __restrict__ Bp, const float* __restrict__ Tprev,
           const float* __restrict__ Gprev,
           const uint32_t* __restrict__ Wh, const uint32_t* __restrict__ Wl,
           const int* __restrict__ from, const int* __restrict__ scat,
           const float* __restrict__ obias,
           float* __restrict__ Gout, float* __restrict__ Acc)
{
    extern __shared__ uint32_t smem[];
    uint32_t* Ah  = smem + OFF_AH;
    uint32_t* Al  = smem + OFF_AL;
    uint32_t* Wsh = smem + OFF_WH;
    uint32_t* Wsl = smem + OFF_WL;

    const int tid = threadIdx.x;

    // ---- stage W hi/lo ONCE ----
#pragma unroll
    for (int i = 0; i < 8; ++i) {
        int f = tid + i * 256;               // 0..2047 uint4s over 8192 words
        int n = f >> 4, c = (f & 15) * 4;
        uint4 vh = *(const uint4*)(Wh + n * 64 + c);
        uint4 vl = *(const uint4*)(Wl + n * 64 + c);
        *(uint4*)(Wsh + n * STR + c) = vh;
        *(uint4*)(Wsl + n * STR + c) = vl;
    }

    const int wid = tid >> 5, lane = tid & 31;
    const int gid = lane >> 2, tig = lane & 3;
    const int wr = wid & 1, wc = wid >> 1;
    const int ar0 = wr * 32, cn0 = wc * 32;

    float obv[8];
    if constexpr (OUT) {
#pragma unroll
        for (int nt = 0; nt < 4; ++nt) {
            obv[2 * nt]     = obias[cn0 + nt * 8 + tig * 2];
            obv[2 * nt + 1] = obias[cn0 + nt * 8 + tig * 2 + 1];
        }
    }

    for (int t = blockIdx.x; t < NTILE; t += NBLK) {
        const int r0 = t * 64;
        __syncthreads();   // previous iteration's MMA reads done (also no-op cost at t0)

        // ---- stage A with fused combine + bf16 split ----
#pragma unroll
        for (int i = 0; i < 8; ++i) {
            int f   = tid + i * 256;             // 0..2047 float4s
            int row = f >> 5, c4 = (f & 31) * 4; // float col
            int e   = r0 + row;
            float4 b = *(const float4*)(Bp + (size_t)e * EH + c4);
            float4 v;
            if constexpr (FIRST) {
                v.x = fmaxf(b.x, 0.f); v.y = fmaxf(b.y, 0.f);
                v.z = fmaxf(b.z, 0.f); v.w = fmaxf(b.w, 0.f);
            } else {
                int u = __ldg(&from[e]);
                float4 tt = *(const float4*)(Tprev + (size_t)u * EH + c4);
                float4 g  = *(const float4*)(Gprev + (size_t)(e ^ 1) * EH + c4);
                v.x = fmaxf(b.x + tt.x - g.x, 0.f);
                v.y = fmaxf(b.y + tt.y - g.y, 0.f);
                v.z = fmaxf(b.z + tt.z - g.z, 0.f);
                v.w = fmaxf(b.w + tt.w - g.w, 0.f);
            }
            uint32_t h0, l0, h1, l1;
            split2(v.x, v.y, h0, l0);
            split2(v.z, v.w, h1, l1);
            int wb = row * STR + (c4 >> 1);
            Ah[wb] = h0; Ah[wb + 1] = h1;
            Al[wb] = l0; Al[wb + 1] = l1;
        }
        __syncthreads();

        // ---- MMA ----
        float acc[2][4][4];
#pragma unroll
        for (int mt = 0; mt < 2; ++mt)
#pragma unroll
            for (int nt = 0; nt < 4; ++nt)
#pragma unroll
                for (int j = 0; j < 4; ++j) acc[mt][nt][j] = 0.f;

#pragma unroll
        for (int ks = 0; ks < 8; ++ks) {          // K = 8 steps * 16
            const int k0w = ks * 8;
            uint32_t ah[2][4], al[2][4];
#pragma unroll
            for (int mt = 0; mt < 2; ++mt) {
                int base = (ar0 + mt * 16 + gid) * STR + k0w + tig;
                ah[mt][0] = Ah[base];
                ah[mt][1] = Ah[base + 8 * STR];
                ah[mt][2] = Ah[base + 4];
                ah[mt][3] = Ah[base + 8 * STR + 4];
                al[mt][0] = Al[base];
                al[mt][1] = Al[base + 8 * STR];
                al[mt][2] = Al[base + 4];
                al[mt][3] = Al[base + 8 * STR + 4];
            }
#pragma unroll
            for (int nt = 0; nt < 4; ++nt) {
                int nb = (cn0 + nt * 8 + gid) * STR + k0w + tig;
                uint32_t bh0 = Wsh[nb], bh1 = Wsh[nb + 4];
                uint32_t bl0 = Wsl[nb], bl1 = Wsl[nb + 4];
                // hi*hi + lo*hi + hi*lo  (3xBF16)
                mma16(acc[0][nt], ah[0], bh0, bh1);
                mma16(acc[1][nt], ah[1], bh0, bh1);
                mma16(acc[0][nt], al[0], bh0, bh1);
                mma16(acc[1][nt], al[1], bh0, bh1);
                mma16(acc[0][nt], ah[0], bl0, bl1);
                mma16(acc[1][nt], ah[1], bl0, bl1);
            }
        }

        // ---- epilogue (gmem only) ----
#pragma unroll
        for (int mt = 0; mt < 2; ++mt) {
#pragma unroll
            for (int half = 0; half < 2; ++half) {
                const int r  = r0 + ar0 + mt * 16 + gid + half * 8;
                const int sc = __ldg(&scat[r]);
                float* ap = Acc + (size_t)sc * EH;
#pragma unroll
                for (int nt = 0; nt < 4; ++nt) {
                    const int col = cn0 + nt * 8 + tig * 2;
                    float x = acc[mt][nt][half * 2 + 0];
                    float y = acc[mt][nt][half * 2 + 1];
                    if constexpr (OUT) {
                        x += obv[2 * nt]; y += obv[2 * nt + 1];
                    } else {
                        *(float2*)(Gout + (size_t)r * EH + col) = make_float2(x, y);
                    }
                    red2(ap + col, x, y);
                }
            }
        }
    }
}

// ============================================================
// Scalar fp32 GEMM (small precompute GEMMs only)
// EPI 0: C = acc + bias ; EPI 1: C = acc + bias + gadd[gidx[row]]
// ============================================================
template <int KTOT, int EPI>
__global__ void __launch_bounds__(256)
gemm_tile(const float* __restrict__ A, const float* __restrict__ W,
          const float* __restrict__ bias, float* __restrict__ C, int M,
          const int* __restrict__ gidx, const float* __restrict__ gadd)
{
    constexpr int KC = (KTOT < 32) ? KTOT : 32;
    __shared__ float As[KC][132];
    __shared__ float Ws[KC][128];

    const int tid = threadIdx.x;
    const int tr  = tid >> 4;
    const int tc  = tid & 15;
    const int r0  = blockIdx.x * 128;

    float acc[8][8];
#pragma unroll
    for (int i = 0; i < 8; ++i)
#pragma unroll
        for (int j = 0; j < 8; ++j) acc[i][j] = 0.f;

    for (int kc0 = 0; kc0 < KTOT; kc0 += KC) {
        __syncthreads();
#pragma unroll
        for (int i = 0; i < KC / 8; ++i) {
            int f  = tid + i * 256;
            int r  = f / (KC / 4);
            int c4 = (f % (KC / 4)) * 4;
            float4 v = make_float4(0.f, 0.f, 0.f, 0.f);
            int gr = r0 + r;
            if (gr < M) v = *(const float4*)(A + (size_t)gr * KTOT + kc0 + c4);
            As[c4 + 0][r] = v.x; As[c4 + 1][r] = v.y;
            As[c4 + 2][r] = v.z; As[c4 + 3][r] = v.w;
        }
#pragma unroll
        for (int i = 0; i < KC / 8; ++i) {
            int f  = tid + i * 256;
            int kr = f >> 5;
            int c4 = (f & 31) * 4;
            *(float4*)(&Ws[kr][c4]) = *(const float4*)(W + (size_t)(kc0 + kr) * EH + c4);
        }
        __syncthreads();
#pragma unroll
        for (int k = 0; k < KC; ++k) {
            float a[8], w[8];
            *(float4*)&a[0] = *(const float4*)&As[k][tr * 8];
            *(float4*)&a[4] = *(const float4*)&As[k][tr * 8 + 4];
            *(float4*)&w[0] = *(const float4*)&Ws[k][tc * 8];
            *(float4*)&w[4] = *(const float4*)&Ws[k][tc * 8 + 4];
#pragma unroll
            for (int i = 0; i < 8; ++i)
#pragma unroll
                for (int j = 0; j < 8; ++j) acc[i][j] += a[i] * w[j];
        }
    }

    float bs[8];
#pragma unroll
    for (int j = 0; j < 8; ++j) bs[j] = bias[tc * 8 + j];

    const int c0 = tc * 8;
#pragma unroll
    for (int i = 0; i < 8; ++i) {
        int r = r0 + tr * 8 + i;
        if (r >= M) continue;
        if constexpr (EPI == 0) {
            float4 v0, v1;
            v0.x = acc[i][0] + bs[0]; v0.y = acc[i][1] + bs[1];
            v0.z = acc[i][2] + bs[2]; v0.w = acc[i][3] + bs[3];
            v1.x = acc[i][4] + bs[4]; v1.y = acc[i][5] + bs[5];
            v1.z = acc[i][6] + bs[6]; v1.w = acc[i][7] + bs[7];
            *(float4*)(C + (size_t)r * EH + c0)     = v0;
            *(float4*)(C + (size_t)r * EH + c0 + 4) = v1;
        } else {
            int u = gidx[r];
            const float* gp = gadd + (size_t)u * EH + c0;
            float4 p0 = *(const float4*)gp;
            float4 p1 = *(const float4*)(gp + 4);
            float4 v0, v1;
            v0.x = acc[i][0] + bs[0] + p0.x; v0.y = acc[i][1] + bs[1] + p0.y;
            v0.z = acc[i][2] + bs[2] + p0.z; v0.w = acc[i][3] + bs[3] + p0.w;
            v1.x = acc[i][4] + bs[4] + p1.x; v1.y = acc[i][5] + bs[5] + p1.y;
            v1.z = acc[i][6] + bs[6] + p1.z; v1.w = acc[i][7] + bs[7] + p1.w;
            *(float4*)(C + (size_t)r * EH + c0)     = v0;
            *(float4*)(C + (size_t)r * EH + c0 + 4) = v1;
        }
    }
}

// out = relu(out + U1x)
__global__ void __launch_bounds__(256)
final_relu(float* __restrict__ out, const float* __restrict__ U1x)
{
    int idx = blockIdx.x * blockDim.x + threadIdx.x;
    if (idx >= NN * EH / 4) return;
    float4 a = ((const float4*)out)[idx];
    float4 b = ((const float4*)U1x)[idx];
    float4 r;
    r.x = fmaxf(a.x + b.x, 0.f);
    r.y = fmaxf(a.y + b.y, 0.f);
    r.z = fmaxf(a.z + b.z, 0.f);
    r.w = fmaxf(a.w + b.w, 0.f);
    ((float4*)out)[idx] = r;
}

extern "C" void kernel_launch(void* const* d_in, const int* in_sizes, int n_in,
                              void* d_out, int out_size)
{
    const float* nf  = (const float*)d_in[0];
    const float* ef  = (const float*)d_in[1];
    const int*   edg = (const int*)  d_in[3];
    const float* W1w = (const float*)d_in[4];
    const float* W1b = (const float*)d_in[5];
    const float* W2w = (const float*)d_in[6];
    const float* W2b = (const float*)d_in[7];
    const float* W3w = (const float*)d_in[8];
    const float* W3b = (const float*)d_in[9];
    const float* U1w = (const float*)d_in[10];
    const float* U1b = (const float*)d_in[11];
    const float* U2w = (const float*)d_in[12];
    const float* U2b = (const float*)d_in[13];

    const int* from = edg;
    const int* to   = edg + NE;

    float *P, *U1x, *B, *G0, *G1, *T0, *T1, *cb;
    uint32_t *W3h, *W3l, *U2h, *U2l;
    cudaGetSymbolAddress((void**)&P,   g_P);
    cudaGetSymbolAddress((void**)&U1x, g_U1);
    cudaGetSymbolAddress((void**)&B,   g_B);
    cudaGetSymbolAddress((void**)&G0,  g_G0);
    cudaGetSymbolAddress((void**)&G1,  g_G1);
    cudaGetSymbolAddress((void**)&T0,  g_T0);
    cudaGetSymbolAddress((void**)&T1,  g_T1);
    cudaGetSymbolAddress((void**)&W3h, g_W3h);
    cudaGetSymbolAddress((void**)&W3l, g_W3l);
    cudaGetSymbolAddress((void**)&U2h, g_U2h);
    cudaGetSymbolAddress((void**)&U2l, g_U2l);
    cudaGetSymbolAddress((void**)&cb,  g_cb);

    cudaFuncSetAttribute(gemm_fused<true,  false>,
                         cudaFuncAttributeMaxDynamicSharedMemorySize, (int)SM_TOT);
    cudaFuncSetAttribute(gemm_fused<false, false>,
                         cudaFuncAttributeMaxDynamicSharedMemorySize, (int)SM_TOT);
    cudaFuncSetAttribute(gemm_fused<false, true>,
                         cudaFuncAttributeMaxDynamicSharedMemorySize, (int)SM_TOT);

    const int gnode = (NN + 127) / 128;
    const int gedge128 = (NE + 127) / 128;

    // weight prep + combined bias (single launch)
    prep_all<<<65, 256>>>(W3w, U2w, W2b, W3b, W3h, W3l, U2h, U2l, cb);

    // loop-invariant precomputes
    gemm_tile<64, 0><<<gnode, 256>>>(nf, W1w, W1b, P,   NN, nullptr, nullptr);
    gemm_tile<64, 0><<<gnode, 256>>>(nf, U1w, U1b, U1x, NN, nullptr, nullptr);
    gemm_tile<16, 1><<<gedge128, 256>>>(ef, W2w, cb, B, NE, from, P);

    // buffers: step s output lives in buffer (s & 1)
    float* Gb[2] = {G0, G1};
    float* Tb[2] = {T0, T1};

    // s = 1: h1 = relu(B'), G = h1@W3, T = seg(G, from)  -> buffer 1
    cudaMemsetAsync(Tb[1], 0, (size_t)NN * EH * sizeof(float));
    gemm_fused<true, false><<<NBLK, 256, SM_TOT>>>(
        B, nullptr, nullptr, W3h, W3l, from, from, nullptr, Gb[1], Tb[1]);

    // s = 2..5: read buffer (s-1)&1, write buffer s&1
    for (int s = 2; s <= 5; ++s) {
        cudaMemsetAsync(Tb[s & 1], 0, (size_t)NN * EH * sizeof(float));
        gemm_fused<false, false><<<NBLK, 256, SM_TOT>>>(
            B, Tb[(s - 1) & 1], Gb[(s - 1) & 1], W3h, W3l, from, from, nullptr,
            Gb[s & 1], Tb[s & 1]);
    }

    // readout: h6 built on the fly from (T5, G5) = buffer 1; red into d_out by `to`
    cudaMemsetAsync(d_out, 0, (size_t)NN * EH * sizeof(float));
    gemm_fused<false, true><<<NBLK, 256, SM_TOT>>>(
        B, Tb[1], Gb[1], U2h, U2l, from, to, U2b, nullptr, (float*)d_out);

    final_relu<<<(NN * EH / 4 + 255) / 256, 256>>>((float*)d_out, U1x);
}

// round 10
// speedup vs baseline: 1.1252x; 1.0254x over previous
#include <cuda_runtime.h>
#include <cuda_bf16.h>
#include <cstdint>
#include <cstddef>

#define NN 100000
#define NE 600000
#define NF 64
#define EF 16
#define EH 128
#define NSTEPS 6
#define NTILE (NE / 64)      // 9375
#define NBLK  296            // 2 CTAs x 148 SMs, persistent

// ---- scratch (device globals; no allocation allowed) ----
__device__ float g_P  [(size_t)NN * EH];   // nf@W1 + b1
__device__ float g_U1 [(size_t)NN * EH];   // nf@U1 + b1
__device__ float g_B  [(size_t)NE * EH];   // B' = P[from] + ef@W2 + b2 + b3
__device__ float g_G0 [(size_t)NE * EH];   // G ping
__device__ float g_G1 [(size_t)NE * EH];   // G pong
__device__ float g_T0 [(size_t)NN * EH];   // T ping
__device__ float g_T1 [(size_t)NN * EH];   // T pong
__device__ uint4 g_W3p[4096];              // W3^T fragment-packed (bh0,bh1,bl0,bl1)
__device__ uint4 g_U2p[4096];              // U2^T fragment-packed
__device__ float g_cb [EH];                // W2_b + W3_b

// ================= helpers =================
__device__ __forceinline__ void mma16(float* c, const uint32_t* a,
                                      uint32_t b0, uint32_t b1) {
    asm volatile(
        "mma.sync.aligned.m16n8k16.row.col.f32.bf16.bf16.f32 "
        "{%0,%1,%2,%3}, {%4,%5,%6,%7}, {%8,%9}, {%0,%1,%2,%3};"
        : "+f"(c[0]), "+f"(c[1]), "+f"(c[2]), "+f"(c[3])
        : "r"(a[0]), "r"(a[1]), "r"(a[2]), "r"(a[3]), "r"(b0), "r"(b1));
}

__device__ __forceinline__ void red2(float* p, float x, float y) {
    asm volatile("red.global.add.v2.f32 [%0], {%1, %2};"
                 :: "l"(p), "f"(x), "f"(y) : "memory");
}

// rn-split (used offline in prep only)
__device__ __forceinline__ void split2(float x, float y, uint32_t& hi, uint32_t& lo) {
    __nv_bfloat162 h = __floats2bfloat162_rn(x, y);
    float2 hf = __bfloat1622float2(h);
    __nv_bfloat162 l = __floats2bfloat162_rn(x - hf.x, y - hf.y);
    hi = *(uint32_t*)&h;
    lo = *(uint32_t*)&l;
}

// fast truncation split: hw = packed hi16(x),hi16(y); lw = bf16x2(residuals)
__device__ __forceinline__ void tsplit(float x, float y, uint32_t& hw, uint32_t& lw) {
    uint32_t xb = __float_as_uint(x), yb = __float_as_uint(y);
    hw = __byte_perm(xb, yb, 0x7632);
    float lx = x - __uint_as_float(xb & 0xFFFF0000u);
    float ly = y - __uint_as_float(yb & 0xFFFF0000u);
    __nv_bfloat162 l2 = __floats2bfloat162_rn(lx, ly);
    lw = *(uint32_t*)&l2;
}

// pack W3^T / U2^T into fragment uint4 layout + combined bias
__global__ void prep_all(const float* __restrict__ W3, const float* __restrict__ U2,
                         const float* __restrict__ W2b, const float* __restrict__ W3b,
                         uint4* __restrict__ W3p, uint4* __restrict__ U2p,
                         float* __restrict__ cb) {
    int b = blockIdx.x, tid = threadIdx.x;
    if (b < 32) {
        const float* W = (b < 16) ? W3 : U2;
        uint4* out = (b < 16) ? W3p : U2p;
        int idx = (b & 15) * 256 + tid;            // 0..4095
        int tig = idx & 3, gid = (idx >> 2) & 7, nt = (idx >> 5) & 3;
        int ks = (idx >> 7) & 7, wc = idx >> 10;
        int n = wc * 32 + nt * 8 + gid;
        int kw0 = ks * 8 + tig, kw1 = kw0 + 4;
        uint32_t bh0, bl0, bh1, bl1;
        split2(W[(2 * kw0) * 128 + n], W[(2 * kw0 + 1) * 128 + n], bh0, bl0);
        split2(W[(2 * kw1) * 128 + n], W[(2 * kw1 + 1) * 128 + n], bh1, bl1);
        out[idx] = make_uint4(bh0, bh1, bl0, bl1);
    } else if (b == 32) {
        if (tid < EH) cb[tid] = W2b[tid] + W3b[tid];
    }
}

// ============================================================
// Fused 3xBF16 MMA GEMM over edges — persistent, fragment-packed smem.
// ============================================================
static constexpr int A_PLANE = 1024;               // uint4 per plane
static constexpr int W_OFF   = 2048;               // uint4 offset of W
static constexpr size_t SM_TOT = (size_t)(2048 + 4096) * 16;   // 98304 B

template <bool FIRST>
__device__ __forceinline__ void stage_row(
    int e, int ks, const float* __restrict__ Bp, const float* __restrict__ Tprev,
    const float* __restrict__ Gprev, const int* __restrict__ from,
    uint32_t* hw, uint32_t* lw)
{
    const float* bp = Bp + (size_t)e * EH + ks * 16;
    float4 b0 = *(const float4*)(bp + 0);
    float4 b1 = *(const float4*)(bp + 4);
    float4 b2 = *(const float4*)(bp + 8);
    float4 b3 = *(const float4*)(bp + 12);
    float v[16];
    if constexpr (FIRST) {
        v[0]=fmaxf(b0.x,0.f); v[1]=fmaxf(b0.y,0.f); v[2]=fmaxf(b0.z,0.f); v[3]=fmaxf(b0.w,0.f);
        v[4]=fmaxf(b1.x,0.f); v[5]=fmaxf(b1.y,0.f); v[6]=fmaxf(b1.z,0.f); v[7]=fmaxf(b1.w,0.f);
        v[8]=fmaxf(b2.x,0.f); v[9]=fmaxf(b2.y,0.f); v[10]=fmaxf(b2.z,0.f); v[11]=fmaxf(b2.w,0.f);
        v[12]=fmaxf(b3.x,0.f); v[13]=fmaxf(b3.y,0.f); v[14]=fmaxf(b3.z,0.f); v[15]=fmaxf(b3.w,0.f);
    } else {
        int u = __ldg(&from[e]);
        const float* tp = Tprev + (size_t)u * EH + ks * 16;
        const float* gp = Gprev + (size_t)(e ^ 1) * EH + ks * 16;
        float4 t0 = *(const float4*)(tp + 0);
        float4 t1 = *(const float4*)(tp + 4);
        float4 t2 = *(const float4*)(tp + 8);
        float4 t3 = *(const float4*)(tp + 12);
        float4 g0 = *(const float4*)(gp + 0);
        float4 g1 = *(const float4*)(gp + 4);
        float4 g2 = *(const float4*)(gp + 8);
        float4 g3 = *(const float4*)(gp + 12);
        v[0]=fmaxf(b0.x+t0.x-g0.x,0.f); v[1]=fmaxf(b0.y+t0.y-g0.y,0.f);
        v[2]=fmaxf(b0.z+t0.z-g0.z,0.f); v[3]=fmaxf(b0.w+t0.w-g0.w,0.f);
        v[4]=fmaxf(b1.x+t1.x-g1.x,0.f); v[5]=fmaxf(b1.y+t1.y-g1.y,0.f);
        v[6]=fmaxf(b1.z+t1.z-g1.z,0.f); v[7]=fmaxf(b1.w+t1.w-g1.w,0.f);
        v[8]=fmaxf(b2.x+t2.x-g2.x,0.f); v[9]=fmaxf(b2.y+t2.y-g2.y,0.f);
        v[10]=fmaxf(b2.z+t2.z-g2.z,0.f); v[11]=fmaxf(b2.w+t2.w-g2.w,0.f);
        v[12]=fmaxf(b3.x+t3.x-g3.x,0.f); v[13]=fmaxf(b3.y+t3.y-g3.y,0.f);
        v[14]=fmaxf(b3.z+t3.z-g3.z,0.f); v[15]=fmaxf(b3.w+t3.w-g3.w,0.f);
    }
#pragma unroll
    for (int j = 0; j < 8; ++j)
        tsplit(v[2 * j], v[2 * j + 1], hw[j], lw[j]);
}

template <bool FIRST, bool OUT>
__global__ void __launch_bounds__(256, 2)
gemm_fused(const float* __restrict__ Bp, const float* __restrict__ Tprev,
           const float* __restrict__ Gprev, const uint4* __restrict__ Wg,
           const int* __restrict__ from, const int* __restrict__ scat,
           const float* __restrict__ obias,
           float* __restrict__ Gout, float* __restrict__ Acc)
{
    extern __shared__ uint4 smem4[];
    uint4* AhP = smem4;
    uint4* AlP = smem4 + A_PLANE;
    uint4* Wp  = smem4 + W_OFF;

    const int tid = threadIdx.x;

    // ---- stage packed W once ----
#pragma unroll
    for (int i = 0; i < 16; ++i) Wp[tid + i * 256] = Wg[tid + i * 256];

    // staging item: (row pair, k-block)
    const int ksI   = tid & 7;
    const int pr    = tid >> 3;        // 0..31
    const int wrmtI = pr >> 3;         // 0..3
    const int gidI  = pr & 7;
    const int raL   = wrmtI * 16 + gidI;
    const int xrI   = ksI & 3;
    const int baseI = ((wrmtI * 8 + ksI) * 8 + gidI) * 4;

    const int wid = tid >> 5, lane = tid & 31;
    const int gid = lane >> 2, tig = lane & 3;
    const int wr = wid & 1, wc = wid >> 1;
    const int ar0 = wr * 32, cn0 = wc * 32;

    float obv[8];
    if constexpr (OUT) {
#pragma unroll
        for (int nt = 0; nt < 4; ++nt) {
            obv[2 * nt]     = obias[cn0 + nt * 8 + tig * 2];
            obv[2 * nt + 1] = obias[cn0 + nt * 8 + tig * 2 + 1];
        }
    }

    for (int t = blockIdx.x; t < NTILE; t += NBLK) {
        const int r0 = t * 64;
        __syncthreads();   // previous MMA reads done

        // ---- stage rows (raL, raL+8), k-block ksI ----
        uint32_t hwa[8], lwa[8], hwb[8], lwb[8];
        stage_row<FIRST>(r0 + raL,     ksI, Bp, Tprev, Gprev, from, hwa, lwa);
        stage_row<FIRST>(r0 + raL + 8, ksI, Bp, Tprev, Gprev, from, hwb, lwb);
#pragma unroll
        for (int q = 0; q < 4; ++q) {
            AhP[baseI + (q ^ xrI)] = make_uint4(hwa[q], hwb[q], hwa[q + 4], hwb[q + 4]);
            AlP[baseI + (q ^ xrI)] = make_uint4(lwa[q], lwb[q], lwa[q + 4], lwb[q + 4]);
        }
        __syncthreads();

        // ---- MMA ----
        float acc[2][4][4];
#pragma unroll
        for (int mt = 0; mt < 2; ++mt)
#pragma unroll
            for (int nt = 0; nt < 4; ++nt)
#pragma unroll
                for (int j = 0; j < 4; ++j) acc[mt][nt][j] = 0.f;

#pragma unroll
        for (int ks = 0; ks < 8; ++ks) {
            const int xr = ks & 3;
            uint4 a_h[2], a_l[2];
#pragma unroll
            for (int mt = 0; mt < 2; ++mt) {
                int ia = (((wr * 2 + mt) * 8 + ks) * 8 + gid) * 4 + (tig ^ xr);
                a_h[mt] = AhP[ia];
                a_l[mt] = AlP[ia];
            }
#pragma unroll
            for (int nt = 0; nt < 4; ++nt) {
                int iw = (((wc * 8 + ks) * 4 + nt) * 8 + gid) * 4 + tig;
                uint4 w4 = Wp[iw];
                // hi*hi + lo*hi + hi*lo  (3xBF16)
                mma16(acc[0][nt], (const uint32_t*)&a_h[0], w4.x, w4.y);
                mma16(acc[1][nt], (const uint32_t*)&a_h[1], w4.x, w4.y);
                mma16(acc[0][nt], (const uint32_t*)&a_l[0], w4.x, w4.y);
                mma16(acc[1][nt], (const uint32_t*)&a_l[1], w4.x, w4.y);
                mma16(acc[0][nt], (const uint32_t*)&a_h[0], w4.z, w4.w);
                mma16(acc[1][nt], (const uint32_t*)&a_h[1], w4.z, w4.w);
            }
        }

        // ---- epilogue ----
#pragma unroll
        for (int mt = 0; mt < 2; ++mt) {
#pragma unroll
            for (int half = 0; half < 2; ++half) {
                const int r  = r0 + ar0 + mt * 16 + gid + half * 8;
                const int sc = __ldg(&scat[r]);
                float* ap = Acc + (size_t)sc * EH;
#pragma unroll
                for (int nt = 0; nt < 4; ++nt) {
                    const int col = cn0 + nt * 8 + tig * 2;
                    float x = acc[mt][nt][half * 2 + 0];
                    float y = acc[mt][nt][half * 2 + 1];
                    if constexpr (OUT) {
                        x += obv[2 * nt]; y += obv[2 * nt + 1];
                    } else {
                        *(float2*)(Gout + (size_t)r * EH + col) = make_float2(x, y);
                    }
                    red2(ap + col, x, y);
                }
            }
        }
    }
}

// ============================================================
// Scalar fp32 GEMM (small precompute GEMMs only)
// ============================================================
template <int KTOT, int EPI>
__global__ void __launch_bounds__(256)
gemm_tile(const float* __restrict__ A, const float* __restrict__ W,
          const float* __restrict__ bias, float* __restrict__ C, int M,
          const int* __restrict__ gidx, const float* __restrict__ gadd)
{
    constexpr int KC = (KTOT < 32) ? KTOT : 32;
    __shared__ float As[KC][132];
    __shared__ float Ws[KC][128];

    const int tid = threadIdx.x;
    const int tr  = tid >> 4;
    const int tc  = tid & 15;
    const int r0  = blockIdx.x * 128;

    float acc[8][8];
#pragma unroll
    for (int i = 0; i < 8; ++i)
#pragma unroll
        for (int j = 0; j < 8; ++j) acc[i][j] = 0.f;

    for (int kc0 = 0; kc0 < KTOT; kc0 += KC) {
        __syncthreads();
#pragma unroll
        for (int i = 0; i < KC / 8; ++i) {
            int f  = tid + i * 256;
            int r  = f / (KC / 4);
            int c4 = (f % (KC / 4)) * 4;
            float4 v = make_float4(0.f, 0.f, 0.f, 0.f);
            int gr = r0 + r;
            if (gr < M) v = *(const float4*)(A + (size_t)gr * KTOT + kc0 + c4);
            As[c4 + 0][r] = v.x; As[c4 + 1][r] = v.y;
            As[c4 + 2][r] = v.z; As[c4 + 3][r] = v.w;
        }
#pragma unroll
        for (int i = 0; i < KC / 8; ++i) {
            int f  = tid + i * 256;
            int kr = f >> 5;
            int c4 = (f & 31) * 4;
            *(float4*)(&Ws[kr][c4]) = *(const float4*)(W + (size_t)(kc0 + kr) * EH + c4);
        }
        __syncthreads();
#pragma unroll
        for (int k = 0; k < KC; ++k) {
            float a[8], w[8];
            *(float4*)&a[0] = *(const float4*)&As[k][tr * 8];
            *(float4*)&a[4] = *(const float4*)&As[k][tr * 8 + 4];
            *(float4*)&w[0] = *(const float4*)&Ws[k][tc * 8];
            *(float4*)&w[4] = *(const float4*)&Ws[k][tc * 8 + 4];
#pragma unroll
            for (int i = 0; i < 8; ++i)
#pragma unroll
                for (int j = 0; j < 8; ++j) acc[i][j] += a[i] * w[j];
        }
    }

    float bs[8];
#pragma unroll
    for (int j = 0; j < 8; ++j) bs[j] = bias[tc * 8 + j];

    const int c0 = tc * 8;
#pragma unroll
    for (int i = 0; i < 8; ++i) {
        int r = r0 + tr * 8 + i;
        if (r >= M) continue;
        if constexpr (EPI == 0) {
            float4 v0, v1;
            v0.x = acc[i][0] + bs[0]; v0.y = acc[i][1] + bs[1];
            v0.z = acc[i][2] + bs[2]; v0.w = acc[i][3] + bs[3];
            v1.x = acc[i][4] + bs[4]; v1.y = acc[i][5] + bs[5];
            v1.z = acc[i][6] + bs[6]; v1.w = acc[i][7] + bs[7];
            *(float4*)(C + (size_t)r * EH + c0)     = v0;
            *(float4*)(C + (size_t)r * EH + c0 + 4) = v1;
        } else {
            int u = gidx[r];
            const float* gp = gadd + (size_t)u * EH + c0;
            float4 p0 = *(const float4*)gp;
            float4 p1 = *(const float4*)(gp + 4);
            float4 v0, v1;
            v0.x = acc[i][0] + bs[0] + p0.x; v0.y = acc[i][1] + bs[1] + p0.y;
            v0.z = acc[i][2] + bs[2] + p0.z; v0.w = acc[i][3] + bs[3] + p0.w;
            v1.x = acc[i][4] + bs[4] + p1.x; v1.y = acc[i][5] + bs[5] + p1.y;
            v1.z = acc[i][6] + bs[6] + p1.z; v1.w = acc[i][7] + bs[7] + p1.w;
            *(float4*)(C + (size_t)r * EH + c0)     = v0;
            *(float4*)(C + (size_t)r * EH + c0 + 4) = v1;
        }
    }
}

// out = relu(out + U1x)
__global__ void __launch_bounds__(256)
final_relu(float* __restrict__ out, const float* __restrict__ U1x)
{
    int idx = blockIdx.x * blockDim.x + threadIdx.x;
    if (idx >= NN * EH / 4) return;
    float4 a = ((const float4*)out)[idx];
    float4 b = ((const float4*)U1x)[idx];
    float4 r;
    r.x = fmaxf(a.x + b.x, 0.f);
    r.y = fmaxf(a.y + b.y, 0.f);
    r.z = fmaxf(a.z + b.z, 0.f);
    r.w = fmaxf(a.w + b.w, 0.f);
    ((float4*)out)[idx] = r;
}

extern "C" void kernel_launch(void* const* d_in, const int* in_sizes, int n_in,
                              void* d_out, int out_size)
{
    const float* nf  = (const float*)d_in[0];
    const float* ef  = (const float*)d_in[1];
    const int*   edg = (const int*)  d_in[3];
    const float* W1w = (const float*)d_in[4];
    const float* W1b = (const float*)d_in[5];
    const float* W2w = (const float*)d_in[6];
    const float* W2b = (const float*)d_in[7];
    const float* W3w = (const float*)d_in[8];
    const float* W3b = (const float*)d_in[9];
    const float* U1w = (const float*)d_in[10];
    const float* U1b = (const float*)d_in[11];
    const float* U2w = (const float*)d_in[12];
    const float* U2b = (const float*)d_in[13];

    const int* from = edg;
    const int* to   = edg + NE;

    float *P, *U1x, *B, *G0, *G1, *T0, *T1, *cb;
    uint4 *W3p, *U2p;
    cudaGetSymbolAddress((void**)&P,   g_P);
    cudaGetSymbolAddress((void**)&U1x, g_U1);
    cudaGetSymbolAddress((void**)&B,   g_B);
    cudaGetSymbolAddress((void**)&G0,  g_G0);
    cudaGetSymbolAddress((void**)&G1,  g_G1);
    cudaGetSymbolAddress((void**)&T0,  g_T0);
    cudaGetSymbolAddress((void**)&T1,  g_T1);
    cudaGetSymbolAddress((void**)&W3p, g_W3p);
    cudaGetSymbolAddress((void**)&U2p, g_U2p);
    cudaGetSymbolAddress((void**)&cb,  g_cb);

    cudaFuncSetAttribute(gemm_fused<true,  false>,
                         cudaFuncAttributeMaxDynamicSharedMemorySize, (int)SM_TOT);
    cudaFuncSetAttribute(gemm_fused<false, false>,
                         cudaFuncAttributeMaxDynamicSharedMemorySize, (int)SM_TOT);
    cudaFuncSetAttribute(gemm_fused<false, true>,
                         cudaFuncAttributeMaxDynamicSharedMemorySize, (int)SM_TOT);

    const int gnode = (NN + 127) / 128;
    const int gedge128 = (NE + 127) / 128;

    // weight prep + combined bias (single launch)
    prep_all<<<33, 256>>>(W3w, U2w, W2b, W3b, W3p, U2p, cb);

    // loop-invariant precomputes
    gemm_tile<64, 0><<<gnode, 256>>>(nf, W1w, W1b, P,   NN, nullptr, nullptr);
    gemm_tile<64, 0><<<gnode, 256>>>(nf, U1w, U1b, U1x, NN, nullptr, nullptr);
    gemm_tile<16, 1><<<gedge128, 256>>>(ef, W2w, cb, B, NE, from, P);

    // buffers: step s output lives in buffer (s & 1)
    float* Gb[2] = {G0, G1};
    float* Tb[2] = {T0, T1};

    // s = 1: h1 = relu(B'), G = h1@W3, T = seg(G, from)  -> buffer 1
    cudaMemsetAsync(Tb[1], 0, (size_t)NN * EH * sizeof(float));
    gemm_fused<true, false><<<NBLK, 256, SM_TOT>>>(
        B, nullptr, nullptr, W3p, from, from, nullptr, Gb[1], Tb[1]);

    // s = 2..5: read buffer (s-1)&1, write buffer s&1
    for (int s = 2; s <= 5; ++s) {
        cudaMemsetAsync(Tb[s & 1], 0, (size_t)NN * EH * sizeof(float));
        gemm_fused<false, false><<<NBLK, 256, SM_TOT>>>(
            B, Tb[(s - 1) & 1], Gb[(s - 1) & 1], W3p, from, from, nullptr,
            Gb[s & 1], Tb[s & 1]);
    }

    // readout: h6 built on the fly from (T5, G5) = buffer 1; red into d_out by `to`
    cudaMemsetAsync(d_out, 0, (size_t)NN * EH * sizeof(float));
    gemm_fused<false, true><<<NBLK, 256, SM_TOT>>>(
        B, Tb[1], Gb[1], U2p, from, to, U2b, nullptr, (float*)d_out);

    final_relu<<<(NN * EH / 4 + 255) / 256, 256>>>((float*)d_out, U1x);
}